// round 10
// baseline (speedup 1.0000x reference)
#include <cuda_runtime.h>
#include <cstdint>

#define EPS 1e-5f
typedef unsigned long long ull;

// ---------------- scratch (device globals; zero-init at load; halos never written) ----------
__device__ __align__(16) float  g_h1[2*34*34*34*32];   // conv1 out, +1 halo all sides, channel-last
__device__ __align__(16) float  g_h2[2*32*32*32*32];   // conv2 out, channel-last [b][z][y][x][ci]
__device__ __align__(16) float  g_h3[2L*274625*100];   // k3 compact out, site-major [b,z,y,x][co]
__device__ unsigned char        g_m1[2*32*32*32];      // conv1 output-site mask
__device__ __align__(16) float  g_w1t[27*32];          // W1  -> [tap][co]
__device__ __align__(16) float2 g_w2t[27*16*32];       // W2  -> [tap][ci/2][co] (ci-pair packed)
__device__ __align__(16) float2 g_wvt[27*16*100];      // Winv-> [tap][ci/2][co]

__device__ __forceinline__ ull ffma2(ull a, ull b, ull c){
    ull d; asm("fma.rn.f32x2 %0, %1, %2, %3;" : "=l"(d) : "l"(a), "l"(b), "l"(c)); return d;
}
__device__ __forceinline__ float pair_sum(ull v){
    float lo = __uint_as_float((unsigned)(v & 0xffffffffu));
    float hi = __uint_as_float((unsigned)(v >> 32));
    return lo + hi;
}

// ---------------- k0: weight transposes -----------------------------------------------------
__global__ void k0_transpose(const float* __restrict__ W1, const float* __restrict__ W2,
                             const float* __restrict__ Wv)
{
    const int N1 = 27*32;
    const int N2 = 27*16*32;
    const int N3 = 27*16*100;
    for (int i = blockIdx.x*blockDim.x + threadIdx.x; i < N1+N2+N3; i += gridDim.x*blockDim.x){
        if (i < N1){
            int tap = i >> 5, co = i & 31;
            g_w1t[i] = W1[co*27 + tap];
        } else if (i < N1+N2){
            int j = i - N1;
            int tap = j / 512, r = j % 512, cp = r >> 5, co = r & 31;
            g_w2t[j] = make_float2(W2[(co*32 + 2*cp    )*27 + tap],
                                   W2[(co*32 + 2*cp + 1)*27 + tap]);
        } else {
            int k = i - N1 - N2;
            int tap = k / 1600, r = k % 1600, cp = r / 100, co = r % 100;
            g_wvt[k] = make_float2(Wv[(co*32 + 2*cp    )*27 + tap],
                                   Wv[(co*32 + 2*cp + 1)*27 + tap]);
        }
    }
}

// ---------------- k1: conv1(s2) + BN + ReLU + mask  -> g_h1, g_m1 ----------------------------
__global__ __launch_bounds__(128)
void k1_conv1(const float* __restrict__ x, const int* __restrict__ mask0,
              const float* __restrict__ b1, const float* __restrict__ g1,
              const float* __restrict__ bt1, const float* __restrict__ rm1,
              const float* __restrict__ rv1)
{
    __shared__ float sin_[9][65];
    __shared__ int   smk[9][65];
    __shared__ float sw[27*32];
    __shared__ float m1f[32];

    const int yy = blockIdx.x, zz = blockIdx.y, b = blockIdx.z;
    const int t = threadIdx.x, co = t & 31, xg = t >> 5;

    for (int i = t; i < 9*65; i += 128){
        int r = i / 65, xx = i % 65;
        int kz = r / 3, ky = r % 3;
        int iz = 2*zz + kz, iy = 2*yy + ky;
        long off = ((long)(b*65 + iz)*65 + iy)*65 + xx;
        sin_[r][xx] = x[off];
        smk[r][xx]  = mask0[off];
    }
    for (int i = t; i < 27*32; i += 128) sw[i] = g_w1t[i];
    __syncthreads();

    if (t < 32){
        int xo = t, m = 0;
        #pragma unroll
        for (int r = 0; r < 9; r++)
            m |= smk[r][2*xo] | smk[r][2*xo+1] | smk[r][2*xo+2];
        m1f[xo] = m ? 1.0f : 0.0f;
        g_m1[((b*32 + zz)*32 + yy)*32 + xo] = m ? 1 : 0;
    }
    __syncthreads();

    const float s  = g1[co] * rsqrtf(rv1[co] + EPS);
    const float bb = bt1[co] - rm1[co]*s;
    const float bc = b1[co];

    for (int i = 0; i < 8; i++){
        int xo = xg + 4*i;
        float acc = 0.f;
        #pragma unroll
        for (int r = 0; r < 9; r++){
            #pragma unroll
            for (int kx = 0; kx < 3; kx++)
                acc = fmaf(sin_[r][2*xo + kx], sw[(r*3 + kx)*32 + co], acc);
        }
        float h = fmaxf((acc + bc)*s + bb, 0.f) * m1f[xo];
        g_h1[(((long)(b*34 + zz+1)*34 + (yy+1))*34 + (xo+1))*32 + co] = h;
    }
}

// ---------------- k2: SubMConv 32->32 + BN + ReLU + mask -> g_h2 (NO fill anymore) -----------
__global__ __launch_bounds__(128)
void k2_conv2(const float* __restrict__ b2, const float* __restrict__ g2,
              const float* __restrict__ bt2, const float* __restrict__ rm2,
              const float* __restrict__ rv2)
{
    __shared__ __align__(16) float sh[9*34*32];
    __shared__ float m1f[32];

    const int yy = blockIdx.x, zz = blockIdx.y, b = blockIdx.z;
    const int t = threadIdx.x, co = t & 31, w = t >> 5;
    const int x0 = w * 8;

    {
        float4* dst = reinterpret_cast<float4*>(sh);
        for (int i = t; i < 2448; i += 128){
            int r = i / 272, rem = i % 272;
            int kz = r / 3, ky = r % 3;
            const float4* src = reinterpret_cast<const float4*>(
                g_h1 + (((long)(b*34 + zz+kz)*34 + (yy+ky))*34)*32);
            dst[r*272 + rem] = src[rem];
        }
        if (t < 32) m1f[t] = g_m1[((b*32 + zz)*32 + yy)*32 + t] ? 1.0f : 0.0f;
    }
    __syncthreads();

    const ull* shu = reinterpret_cast<const ull*>(sh);
    const ull* w2u = reinterpret_cast<const ull*>(g_w2t);
    ull acc[8];
    #pragma unroll
    for (int j = 0; j < 8; j++) acc[j] = 0;

    for (int row = 0; row < 9; row++){
        const ull* base = shu + (row*34 + x0)*16;
        const ull* wb   = w2u + row*3*512 + co;
        #pragma unroll
        for (int cp = 0; cp < 16; cp++){
            ull h[10];
            #pragma unroll
            for (int i = 0; i < 10; i++) h[i] = base[i*16 + cp];
            ull w0 = __ldg(wb +        cp*32);
            ull w1 = __ldg(wb + 512  + cp*32);
            ull w2v= __ldg(wb + 1024 + cp*32);
            #pragma unroll
            for (int j = 0; j < 8; j++){
                acc[j] = ffma2(h[j  ], w0,  acc[j]);
                acc[j] = ffma2(h[j+1], w1,  acc[j]);
                acc[j] = ffma2(h[j+2], w2v, acc[j]);
            }
        }
    }

    const float s  = g2[co] * rsqrtf(rv2[co] + EPS);
    const float bb = bt2[co] - rm2[co]*s;
    const float bc = b2[co];
    float* out = g_h2 + (((long)(b*32 + zz)*32 + yy)*32)*32;
    #pragma unroll
    for (int j = 0; j < 8; j++){
        float v = fmaxf((pair_sum(acc[j]) + bc)*s + bb, 0.f) * m1f[x0+j];
        out[(x0+j)*32 + co] = v;
    }
}

// ---------------- k3 v8: R8 structure, but COMPACT coalesced writes to g_h3 ------------------
// grid (33 z-slices, 8 parity classes, 2 b), 512 threads: slot=t>>7, co=t&127 (<100 active)
#define K3_CH 64
__global__ __launch_bounds__(512)
void k3_inv(const int* __restrict__ mask0, const float* __restrict__ binv)
{
    __shared__ __align__(16) ulonglong2 hS[K3_CH*8];   // 8KB gathered h tile
    __shared__ unsigned short alist[1089];
    __shared__ int s_na;

    const int cls = blockIdx.y;
    const int pz = cls >> 2, py = (cls >> 1) & 1, px = cls & 1;
    const int zz = pz + 2*(int)blockIdx.x;
    const int b  = blockIdx.z;
    if (zz > 64) return;

    const int nKZ = pz ? 1 : 2;
    const int nKY = py ? 1 : 2;
    const int nKX = px ? 1 : 2;
    const int nT  = nKZ*nKY*nKX;
    const int nyx = nKY*nKX;
    const int t = threadIdx.x;
    const int slot = t >> 7, co = t & 127;

    if (t == 0) s_na = 0;
    __syncthreads();

    const int nYc = py ? 32 : 33;
    const int nXc = px ? 32 : 33;
    const long plane = 274625L;              // 65^3
    const long zbase = (long)b*plane + (long)zz*4225;
    for (int f = t; f < nYc*nXc; f += 512){
        int j = f / nXc, i = f - j*nXc;
        int yy = py + 2*j, xx = px + 2*i;
        if (mask0[zbase + yy*65 + xx]){
            int p = atomicAdd(&s_na, 1);
            alist[p] = (unsigned short)((yy << 8) | xx);
        }
    }
    __syncthreads();
    const int na = s_na;
    if (na == 0) return;

    const float bc = (co < 100) ? binv[co] : 0.f;
    const ulonglong2* h2u2 = reinterpret_cast<const ulonglong2*>(g_h2);
    const ull*        wvtU = reinterpret_cast<const ull*>(g_wvt);

    for (int c0 = 0; c0 < na; c0 += K3_CH){
        const int nc = min(K3_CH, na - c0);
        ull acc[16];
        #pragma unroll
        for (int j = 0; j < 16; j++) acc[j] = 0;

        for (int ti = 0; ti < nT; ti++){
            const int zi = ti / nyx, rr = ti - zi*nyx;
            const int yi = rr / nKX, xi = rr - (rr/nKX)*nKX;
            const int q0 = pz ? ((zz-1) >> 1) : ((zz >> 1) - 1 + zi);
            if ((unsigned)q0 > 31u) continue;       // block-uniform
            const int kz = pz ? 1 : 2*zi;
            const int ky = py ? 1 : 2*yi;
            const int kx = px ? 1 : 2*xi;
            const int tap = (kz*3 + ky)*3 + kx;

            __syncthreads();                        // prev-tap compute done reading hS
            {   // stage gathered h tile: nc sites x 128B, 8 threads/site, zeros if invalid
                const int site = t >> 3, part = t & 7;
                if (site < nc){
                    const int sv = alist[c0 + site];
                    const int yy = sv >> 8, xx = sv & 255;
                    const int q1 = py ? ((yy-1) >> 1) : ((yy >> 1) - 1 + yi);
                    const int qx = px ? ((xx-1) >> 1) : ((xx >> 1) - 1 + xi);
                    ulonglong2 v = make_ulonglong2(0ULL, 0ULL);
                    if (((unsigned)q1 <= 31u) & ((unsigned)qx <= 31u))
                        v = __ldg(h2u2 + ((((long)(b*32 + q0)*32 + q1)*32 + qx)*8 + part));
                    hS[site*8 + part] = v;
                }
            }
            __syncthreads();

            if (co < 100){
                ull wr[16];
                const ull* wp = wvtU + tap*1600 + co;
                #pragma unroll
                for (int cp = 0; cp < 16; cp++) wr[cp] = __ldg(wp + cp*100);

                #pragma unroll
                for (int j = 0; j < 16; j++){
                    const int ii = slot + 4*j;
                    if (ii < nc){
                        const ulonglong2* hp = hS + ii*8;
                        ull a = acc[j];
                        #pragma unroll
                        for (int k = 0; k < 4; k++){
                            ulonglong2 u = hp[2*k];
                            ulonglong2 v = hp[2*k + 1];
                            a = ffma2(u.x, wr[4*k+0], a);
                            a = ffma2(u.y, wr[4*k+1], a);
                            a = ffma2(v.x, wr[4*k+2], a);
                            a = ffma2(v.y, wr[4*k+3], a);
                        }
                        acc[j] = a;
                    }
                }
            }
        }

        if (co < 100){
            #pragma unroll
            for (int j = 0; j < 16; j++){
                const int ii = slot + 4*j;
                if (ii < nc){
                    const int sv = alist[c0 + ii];
                    const long site = zbase + (long)(sv >> 8)*65 + (sv & 255);
                    g_h3[site*100 + co] = pair_sum(acc[j]) + bc;   // coalesced 400B/site
                }
            }
        }
    }
}

// ---------------- k4: expand/transpose compact g_h3 -> dense out (streaming) -----------------
// grid (65 y, 65 z, 2 b), 128 threads; smem transpose with pad-101 (conflict-free)
__global__ __launch_bounds__(128)
void k4_expand(const int* __restrict__ mask0, float* __restrict__ out)
{
    __shared__ float v[65*101];
    __shared__ int mrow[65];

    const int yy = blockIdx.x, zz = blockIdx.y, b = blockIdx.z;
    const int t = threadIdx.x;
    const long plane = 274625L;
    const long rowbase = (long)b*plane + (long)zz*4225 + (long)yy*65;

    if (t < 65) mrow[t] = mask0[rowbase + t];
    __syncthreads();

    // load phase: active sites from g_h3 (coalesced 400B bursts), inactive -> 0
    for (int i = t; i < 6500; i += 128){
        int x = i / 100, co = i - x*100;
        float val = 0.f;
        if (mrow[x]) val = g_h3[(rowbase + x)*100 + co];
        v[x*101 + co] = val;
    }
    __syncthreads();

    // store phase: out[b][co][z][y][x], coalesced along x
    float* ob = out + (long)b*100*plane + (long)zz*4225 + (long)yy*65;
    for (int i = t; i < 6500; i += 128){
        int co = i / 65, x = i - co*65;
        ob[(long)co*plane + x] = v[x*101 + co];
    }
}

// ---------------- launch ---------------------------------------------------------------------
extern "C" void kernel_launch(void* const* d_in, const int* in_sizes, int n_in,
                              void* d_out, int out_size)
{
    const float* x     = (const float*)d_in[0];
    const int*   mask0 = (const int*)  d_in[1];
    const float* W1    = (const float*)d_in[2];
    const float* b1    = (const float*)d_in[3];
    const float* g1    = (const float*)d_in[4];
    const float* bt1   = (const float*)d_in[5];
    const float* rm1   = (const float*)d_in[6];
    const float* rv1   = (const float*)d_in[7];
    const float* W2    = (const float*)d_in[8];
    const float* b2    = (const float*)d_in[9];
    const float* g2    = (const float*)d_in[10];
    const float* bt2   = (const float*)d_in[11];
    const float* rm2   = (const float*)d_in[12];
    const float* rv2   = (const float*)d_in[13];
    const float* Winv  = (const float*)d_in[14];
    const float* binv  = (const float*)d_in[15];
    float* out = (float*)d_out;

    k0_transpose<<<64, 256>>>(W1, W2, Winv);
    k1_conv1<<<dim3(32,32,2), 128>>>(x, mask0, b1, g1, bt1, rm1, rv1);
    k2_conv2<<<dim3(32,32,2), 128>>>(b2, g2, bt2, rm2, rv2);
    k3_inv  <<<dim3(33,8,2), 512>>>(mask0, binv);
    k4_expand<<<dim3(65,65,2), 128>>>(mask0, out);
}

// round 11
// speedup vs baseline: 1.0048x; 1.0048x over previous
#include <cuda_runtime.h>
#include <cstdint>

#define EPS 1e-5f
typedef unsigned long long ull;

// ---------------- scratch (device globals; zero-init at load; halos never written) ----------
__device__ __align__(16) float  g_h1[2*34*34*34*32];   // conv1 out, +1 halo all sides, channel-last
__device__ __align__(16) float  g_h2[2*32*32*32*32];   // conv2 out, channel-last [b][z][y][x][ci]
__device__ __align__(16) float  g_h3[2L*274625*100];   // k3 compact out, site-major [b,z,y,x][co]
__device__ unsigned char        g_m1[2*32*32*32];      // conv1 output-site mask
__device__ __align__(16) float  g_w1t[27*32];          // W1  -> [tap][co]
__device__ __align__(16) float2 g_w2t[27*16*32];       // W2  -> [tap][ci/2][co] (ci-pair packed)
__device__ __align__(16) float2 g_wvt[27*16*100];      // Winv-> [tap][ci/2][co]

__device__ __forceinline__ ull ffma2(ull a, ull b, ull c){
    ull d; asm("fma.rn.f32x2 %0, %1, %2, %3;" : "=l"(d) : "l"(a), "l"(b), "l"(c)); return d;
}
__device__ __forceinline__ float pair_sum(ull v){
    float lo = __uint_as_float((unsigned)(v & 0xffffffffu));
    float hi = __uint_as_float((unsigned)(v >> 32));
    return lo + hi;
}

// ---------------- k0: weight transposes -----------------------------------------------------
__global__ void k0_transpose(const float* __restrict__ W1, const float* __restrict__ W2,
                             const float* __restrict__ Wv)
{
    const int N1 = 27*32;
    const int N2 = 27*16*32;
    const int N3 = 27*16*100;
    for (int i = blockIdx.x*blockDim.x + threadIdx.x; i < N1+N2+N3; i += gridDim.x*blockDim.x){
        if (i < N1){
            int tap = i >> 5, co = i & 31;
            g_w1t[i] = W1[co*27 + tap];
        } else if (i < N1+N2){
            int j = i - N1;
            int tap = j / 512, r = j % 512, cp = r >> 5, co = r & 31;
            g_w2t[j] = make_float2(W2[(co*32 + 2*cp    )*27 + tap],
                                   W2[(co*32 + 2*cp + 1)*27 + tap]);
        } else {
            int k = i - N1 - N2;
            int tap = k / 1600, r = k % 1600, cp = r / 100, co = r % 100;
            g_wvt[k] = make_float2(Wv[(co*32 + 2*cp    )*27 + tap],
                                   Wv[(co*32 + 2*cp + 1)*27 + tap]);
        }
    }
}

// ---------------- k1: conv1(s2) + BN + ReLU + mask  -> g_h1, g_m1 ----------------------------
__global__ __launch_bounds__(128)
void k1_conv1(const float* __restrict__ x, const int* __restrict__ mask0,
              const float* __restrict__ b1, const float* __restrict__ g1,
              const float* __restrict__ bt1, const float* __restrict__ rm1,
              const float* __restrict__ rv1)
{
    __shared__ float sin_[9][65];
    __shared__ int   smk[9][65];
    __shared__ float sw[27*32];
    __shared__ float m1f[32];

    const int yy = blockIdx.x, zz = blockIdx.y, b = blockIdx.z;
    const int t = threadIdx.x, co = t & 31, xg = t >> 5;

    for (int i = t; i < 9*65; i += 128){
        int r = i / 65, xx = i % 65;
        int kz = r / 3, ky = r % 3;
        int iz = 2*zz + kz, iy = 2*yy + ky;
        long off = ((long)(b*65 + iz)*65 + iy)*65 + xx;
        sin_[r][xx] = x[off];
        smk[r][xx]  = mask0[off];
    }
    for (int i = t; i < 27*32; i += 128) sw[i] = g_w1t[i];
    __syncthreads();

    if (t < 32){
        int xo = t, m = 0;
        #pragma unroll
        for (int r = 0; r < 9; r++)
            m |= smk[r][2*xo] | smk[r][2*xo+1] | smk[r][2*xo+2];
        m1f[xo] = m ? 1.0f : 0.0f;
        g_m1[((b*32 + zz)*32 + yy)*32 + xo] = m ? 1 : 0;
    }
    __syncthreads();

    const float s  = g1[co] * rsqrtf(rv1[co] + EPS);
    const float bb = bt1[co] - rm1[co]*s;
    const float bc = b1[co];

    for (int i = 0; i < 8; i++){
        int xo = xg + 4*i;
        float acc = 0.f;
        #pragma unroll
        for (int r = 0; r < 9; r++){
            #pragma unroll
            for (int kx = 0; kx < 3; kx++)
                acc = fmaf(sin_[r][2*xo + kx], sw[(r*3 + kx)*32 + co], acc);
        }
        float h = fmaxf((acc + bc)*s + bb, 0.f) * m1f[xo];
        g_h1[(((long)(b*34 + zz+1)*34 + (yy+1))*34 + (xo+1))*32 + co] = h;
    }
}

// ---------------- k2: SubMConv 32->32 + BN + ReLU + mask -> g_h2 (NO fill anymore) -----------
__global__ __launch_bounds__(128)
void k2_conv2(const float* __restrict__ b2, const float* __restrict__ g2,
              const float* __restrict__ bt2, const float* __restrict__ rm2,
              const float* __restrict__ rv2)
{
    __shared__ __align__(16) float sh[9*34*32];
    __shared__ float m1f[32];

    const int yy = blockIdx.x, zz = blockIdx.y, b = blockIdx.z;
    const int t = threadIdx.x, co = t & 31, w = t >> 5;
    const int x0 = w * 8;

    {
        float4* dst = reinterpret_cast<float4*>(sh);
        for (int i = t; i < 2448; i += 128){
            int r = i / 272, rem = i % 272;
            int kz = r / 3, ky = r % 3;
            const float4* src = reinterpret_cast<const float4*>(
                g_h1 + (((long)(b*34 + zz+kz)*34 + (yy+ky))*34)*32);
            dst[r*272 + rem] = src[rem];
        }
        if (t < 32) m1f[t] = g_m1[((b*32 + zz)*32 + yy)*32 + t] ? 1.0f : 0.0f;
    }
    __syncthreads();

    const ull* shu = reinterpret_cast<const ull*>(sh);
    const ull* w2u = reinterpret_cast<const ull*>(g_w2t);
    ull acc[8];
    #pragma unroll
    for (int j = 0; j < 8; j++) acc[j] = 0;

    for (int row = 0; row < 9; row++){
        const ull* base = shu + (row*34 + x0)*16;
        const ull* wb   = w2u + row*3*512 + co;
        #pragma unroll
        for (int cp = 0; cp < 16; cp++){
            ull h[10];
            #pragma unroll
            for (int i = 0; i < 10; i++) h[i] = base[i*16 + cp];
            ull w0 = __ldg(wb +        cp*32);
            ull w1 = __ldg(wb + 512  + cp*32);
            ull w2v= __ldg(wb + 1024 + cp*32);
            #pragma unroll
            for (int j = 0; j < 8; j++){
                acc[j] = ffma2(h[j  ], w0,  acc[j]);
                acc[j] = ffma2(h[j+1], w1,  acc[j]);
                acc[j] = ffma2(h[j+2], w2v, acc[j]);
            }
        }
    }

    const float s  = g2[co] * rsqrtf(rv2[co] + EPS);
    const float bb = bt2[co] - rm2[co]*s;
    const float bc = b2[co];
    float* out = g_h2 + (((long)(b*32 + zz)*32 + yy)*32)*32;
    #pragma unroll
    for (int j = 0; j < 8; j++){
        float v = fmaxf((pair_sum(acc[j]) + bc)*s + bb, 0.f) * m1f[x0+j];
        out[(x0+j)*32 + co] = v;
    }
}

// ---------------- k3 v8: R8 structure, but COMPACT coalesced writes to g_h3 ------------------
// grid (33 z-slices, 8 parity classes, 2 b), 512 threads: slot=t>>7, co=t&127 (<100 active)
#define K3_CH 64
__global__ __launch_bounds__(512)
void k3_inv(const int* __restrict__ mask0, const float* __restrict__ binv)
{
    __shared__ __align__(16) ulonglong2 hS[K3_CH*8];   // 8KB gathered h tile
    __shared__ unsigned short alist[1089];
    __shared__ int s_na;

    const int cls = blockIdx.y;
    const int pz = cls >> 2, py = (cls >> 1) & 1, px = cls & 1;
    const int zz = pz + 2*(int)blockIdx.x;
    const int b  = blockIdx.z;
    if (zz > 64) return;

    const int nKZ = pz ? 1 : 2;
    const int nKY = py ? 1 : 2;
    const int nKX = px ? 1 : 2;
    const int nT  = nKZ*nKY*nKX;
    const int nyx = nKY*nKX;
    const int t = threadIdx.x;
    const int slot = t >> 7, co = t & 127;

    if (t == 0) s_na = 0;
    __syncthreads();

    const int nYc = py ? 32 : 33;
    const int nXc = px ? 32 : 33;
    const long plane = 274625L;              // 65^3
    const long zbase = (long)b*plane + (long)zz*4225;
    for (int f = t; f < nYc*nXc; f += 512){
        int j = f / nXc, i = f - j*nXc;
        int yy = py + 2*j, xx = px + 2*i;
        if (mask0[zbase + yy*65 + xx]){
            int p = atomicAdd(&s_na, 1);
            alist[p] = (unsigned short)((yy << 8) | xx);
        }
    }
    __syncthreads();
    const int na = s_na;
    if (na == 0) return;

    const float bc = (co < 100) ? binv[co] : 0.f;
    const ulonglong2* h2u2 = reinterpret_cast<const ulonglong2*>(g_h2);
    const ull*        wvtU = reinterpret_cast<const ull*>(g_wvt);

    for (int c0 = 0; c0 < na; c0 += K3_CH){
        const int nc = min(K3_CH, na - c0);
        ull acc[16];
        #pragma unroll
        for (int j = 0; j < 16; j++) acc[j] = 0;

        for (int ti = 0; ti < nT; ti++){
            const int zi = ti / nyx, rr = ti - zi*nyx;
            const int yi = rr / nKX, xi = rr - (rr/nKX)*nKX;
            const int q0 = pz ? ((zz-1) >> 1) : ((zz >> 1) - 1 + zi);
            if ((unsigned)q0 > 31u) continue;       // block-uniform
            const int kz = pz ? 1 : 2*zi;
            const int ky = py ? 1 : 2*yi;
            const int kx = px ? 1 : 2*xi;
            const int tap = (kz*3 + ky)*3 + kx;

            __syncthreads();                        // prev-tap compute done reading hS
            {   // stage gathered h tile: nc sites x 128B, 8 threads/site, zeros if invalid
                const int site = t >> 3, part = t & 7;
                if (site < nc){
                    const int sv = alist[c0 + site];
                    const int yy = sv >> 8, xx = sv & 255;
                    const int q1 = py ? ((yy-1) >> 1) : ((yy >> 1) - 1 + yi);
                    const int qx = px ? ((xx-1) >> 1) : ((xx >> 1) - 1 + xi);
                    ulonglong2 v = make_ulonglong2(0ULL, 0ULL);
                    if (((unsigned)q1 <= 31u) & ((unsigned)qx <= 31u))
                        v = __ldg(h2u2 + ((((long)(b*32 + q0)*32 + q1)*32 + qx)*8 + part));
                    hS[site*8 + part] = v;
                }
            }
            __syncthreads();

            if (co < 100){
                ull wr[16];
                const ull* wp = wvtU + tap*1600 + co;
                #pragma unroll
                for (int cp = 0; cp < 16; cp++) wr[cp] = __ldg(wp + cp*100);

                #pragma unroll
                for (int j = 0; j < 16; j++){
                    const int ii = slot + 4*j;
                    if (ii < nc){
                        const ulonglong2* hp = hS + ii*8;
                        ull a = acc[j];
                        #pragma unroll
                        for (int k = 0; k < 4; k++){
                            ulonglong2 u = hp[2*k];
                            ulonglong2 v = hp[2*k + 1];
                            a = ffma2(u.x, wr[4*k+0], a);
                            a = ffma2(u.y, wr[4*k+1], a);
                            a = ffma2(v.x, wr[4*k+2], a);
                            a = ffma2(v.y, wr[4*k+3], a);
                        }
                        acc[j] = a;
                    }
                }
            }
        }

        if (co < 100){
            #pragma unroll
            for (int j = 0; j < 16; j++){
                const int ii = slot + 4*j;
                if (ii < nc){
                    const int sv = alist[c0 + ii];
                    const long site = zbase + (long)(sv >> 8)*65 + (sv & 255);
                    g_h3[site*100 + co] = pair_sum(acc[j]) + bc;   // coalesced 400B/site
                }
            }
        }
    }
}

// ---------------- k4: expand/transpose compact g_h3 -> dense out (streaming) -----------------
// grid (65 y, 65 z, 2 b), 128 threads; smem transpose with pad-101 (conflict-free)
__global__ __launch_bounds__(128)
void k4_expand(const int* __restrict__ mask0, float* __restrict__ out)
{
    __shared__ float v[65*101];
    __shared__ int mrow[65];

    const int yy = blockIdx.x, zz = blockIdx.y, b = blockIdx.z;
    const int t = threadIdx.x;
    const long plane = 274625L;
    const long rowbase = (long)b*plane + (long)zz*4225 + (long)yy*65;

    if (t < 65) mrow[t] = mask0[rowbase + t];
    __syncthreads();

    // load phase: active sites from g_h3 (coalesced 400B bursts), inactive -> 0
    for (int i = t; i < 6500; i += 128){
        int x = i / 100, co = i - x*100;
        float val = 0.f;
        if (mrow[x]) val = g_h3[(rowbase + x)*100 + co];
        v[x*101 + co] = val;
    }
    __syncthreads();

    // store phase: out[b][co][z][y][x], coalesced along x
    float* ob = out + (long)b*100*plane + (long)zz*4225 + (long)yy*65;
    for (int i = t; i < 6500; i += 128){
        int co = i / 65, x = i - co*65;
        ob[(long)co*plane + x] = v[x*101 + co];
    }
}

// ---------------- launch ---------------------------------------------------------------------
extern "C" void kernel_launch(void* const* d_in, const int* in_sizes, int n_in,
                              void* d_out, int out_size)
{
    const float* x     = (const float*)d_in[0];
    const int*   mask0 = (const int*)  d_in[1];
    const float* W1    = (const float*)d_in[2];
    const float* b1    = (const float*)d_in[3];
    const float* g1    = (const float*)d_in[4];
    const float* bt1   = (const float*)d_in[5];
    const float* rm1   = (const float*)d_in[6];
    const float* rv1   = (const float*)d_in[7];
    const float* W2    = (const float*)d_in[8];
    const float* b2    = (const float*)d_in[9];
    const float* g2    = (const float*)d_in[10];
    const float* bt2   = (const float*)d_in[11];
    const float* rm2   = (const float*)d_in[12];
    const float* rv2   = (const float*)d_in[13];
    const float* Winv  = (const float*)d_in[14];
    const float* binv  = (const float*)d_in[15];
    float* out = (float*)d_out;

    k0_transpose<<<64, 256>>>(W1, W2, Winv);
    k1_conv1<<<dim3(32,32,2), 128>>>(x, mask0, b1, g1, bt1, rm1, rv1);
    k2_conv2<<<dim3(32,32,2), 128>>>(b2, g2, bt2, rm2, rv2);
    k3_inv  <<<dim3(33,8,2), 512>>>(mask0, binv);
    k4_expand<<<dim3(65,65,2), 128>>>(mask0, out);
}

// round 12
// speedup vs baseline: 1.1269x; 1.1215x over previous
#include <cuda_runtime.h>
#include <cstdint>

#define EPS 1e-5f
typedef unsigned long long ull;

// ---------------- scratch (device globals; zero-init at load; halos never written) ----------
__device__ __align__(16) float  g_h1[2*34*34*34*32];   // conv1 out, +1 halo all sides, channel-last
__device__ __align__(16) float  g_h2[2*32*32*32*32];   // conv2 out, channel-last [b][z][y][x][ci]
__device__ __align__(16) float  g_h3[2L*274625*100];   // k3 compact out, site-major [b,z,y,x][co]
__device__ unsigned char        g_m1[2*32*32*32];      // conv1 output-site mask
__device__ __align__(16) float  g_w1t[27*32];          // W1  -> [tap][co]
__device__ __align__(16) float2 g_w2t[27*16*32];       // W2  -> [tap][ci/2][co] (ci-pair packed)
__device__ __align__(16) float2 g_wvt[27*16*100];      // Winv-> [tap][ci/2][co]

__device__ __forceinline__ ull ffma2(ull a, ull b, ull c){
    ull d; asm("fma.rn.f32x2 %0, %1, %2, %3;" : "=l"(d) : "l"(a), "l"(b), "l"(c)); return d;
}
__device__ __forceinline__ float pair_sum(ull v){
    float lo = __uint_as_float((unsigned)(v & 0xffffffffu));
    float hi = __uint_as_float((unsigned)(v >> 32));
    return lo + hi;
}

// ---------------- k0: weight transposes -----------------------------------------------------
__global__ void k0_transpose(const float* __restrict__ W1, const float* __restrict__ W2,
                             const float* __restrict__ Wv)
{
    const int N1 = 27*32;
    const int N2 = 27*16*32;
    const int N3 = 27*16*100;
    for (int i = blockIdx.x*blockDim.x + threadIdx.x; i < N1+N2+N3; i += gridDim.x*blockDim.x){
        if (i < N1){
            int tap = i >> 5, co = i & 31;
            g_w1t[i] = W1[co*27 + tap];
        } else if (i < N1+N2){
            int j = i - N1;
            int tap = j / 512, r = j % 512, cp = r >> 5, co = r & 31;
            g_w2t[j] = make_float2(W2[(co*32 + 2*cp    )*27 + tap],
                                   W2[(co*32 + 2*cp + 1)*27 + tap]);
        } else {
            int k = i - N1 - N2;
            int tap = k / 1600, r = k % 1600, cp = r / 100, co = r % 100;
            g_wvt[k] = make_float2(Wv[(co*32 + 2*cp    )*27 + tap],
                                   Wv[(co*32 + 2*cp + 1)*27 + tap]);
        }
    }
}

// ---------------- k1: conv1(s2) + BN + ReLU + mask  -> g_h1, g_m1 ----------------------------
__global__ __launch_bounds__(128)
void k1_conv1(const float* __restrict__ x, const int* __restrict__ mask0,
              const float* __restrict__ b1, const float* __restrict__ g1,
              const float* __restrict__ bt1, const float* __restrict__ rm1,
              const float* __restrict__ rv1)
{
    __shared__ float sin_[9][65];
    __shared__ int   smk[9][65];
    __shared__ float sw[27*32];
    __shared__ float m1f[32];

    const int yy = blockIdx.x, zz = blockIdx.y, b = blockIdx.z;
    const int t = threadIdx.x, co = t & 31, xg = t >> 5;

    for (int i = t; i < 9*65; i += 128){
        int r = i / 65, xx = i % 65;
        int kz = r / 3, ky = r % 3;
        int iz = 2*zz + kz, iy = 2*yy + ky;
        long off = ((long)(b*65 + iz)*65 + iy)*65 + xx;
        sin_[r][xx] = x[off];
        smk[r][xx]  = mask0[off];
    }
    for (int i = t; i < 27*32; i += 128) sw[i] = g_w1t[i];
    __syncthreads();

    if (t < 32){
        int xo = t, m = 0;
        #pragma unroll
        for (int r = 0; r < 9; r++)
            m |= smk[r][2*xo] | smk[r][2*xo+1] | smk[r][2*xo+2];
        m1f[xo] = m ? 1.0f : 0.0f;
        g_m1[((b*32 + zz)*32 + yy)*32 + xo] = m ? 1 : 0;
    }
    __syncthreads();

    const float s  = g1[co] * rsqrtf(rv1[co] + EPS);
    const float bb = bt1[co] - rm1[co]*s;
    const float bc = b1[co];

    for (int i = 0; i < 8; i++){
        int xo = xg + 4*i;
        float acc = 0.f;
        #pragma unroll
        for (int r = 0; r < 9; r++){
            #pragma unroll
            for (int kx = 0; kx < 3; kx++)
                acc = fmaf(sin_[r][2*xo + kx], sw[(r*3 + kx)*32 + co], acc);
        }
        float h = fmaxf((acc + bc)*s + bb, 0.f) * m1f[xo];
        g_h1[(((long)(b*34 + zz+1)*34 + (yy+1))*34 + (xo+1))*32 + co] = h;
    }
}

// ---------------- k2: SubMConv 32->32 + BN + ReLU + mask -> g_h2 -----------------------------
__global__ __launch_bounds__(128)
void k2_conv2(const float* __restrict__ b2, const float* __restrict__ g2,
              const float* __restrict__ bt2, const float* __restrict__ rm2,
              const float* __restrict__ rv2)
{
    __shared__ __align__(16) float sh[9*34*32];
    __shared__ float m1f[32];

    const int yy = blockIdx.x, zz = blockIdx.y, b = blockIdx.z;
    const int t = threadIdx.x, co = t & 31, w = t >> 5;
    const int x0 = w * 8;

    {
        float4* dst = reinterpret_cast<float4*>(sh);
        for (int i = t; i < 2448; i += 128){
            int r = i / 272, rem = i % 272;
            int kz = r / 3, ky = r % 3;
            const float4* src = reinterpret_cast<const float4*>(
                g_h1 + (((long)(b*34 + zz+kz)*34 + (yy+ky))*34)*32);
            dst[r*272 + rem] = src[rem];
        }
        if (t < 32) m1f[t] = g_m1[((b*32 + zz)*32 + yy)*32 + t] ? 1.0f : 0.0f;
    }
    __syncthreads();

    const ull* shu = reinterpret_cast<const ull*>(sh);
    const ull* w2u = reinterpret_cast<const ull*>(g_w2t);
    ull acc[8];
    #pragma unroll
    for (int j = 0; j < 8; j++) acc[j] = 0;

    for (int row = 0; row < 9; row++){
        const ull* base = shu + (row*34 + x0)*16;
        const ull* wb   = w2u + row*3*512 + co;
        #pragma unroll
        for (int cp = 0; cp < 16; cp++){
            ull h[10];
            #pragma unroll
            for (int i = 0; i < 10; i++) h[i] = base[i*16 + cp];
            ull w0 = __ldg(wb +        cp*32);
            ull w1 = __ldg(wb + 512  + cp*32);
            ull w2v= __ldg(wb + 1024 + cp*32);
            #pragma unroll
            for (int j = 0; j < 8; j++){
                acc[j] = ffma2(h[j  ], w0,  acc[j]);
                acc[j] = ffma2(h[j+1], w1,  acc[j]);
                acc[j] = ffma2(h[j+2], w2v, acc[j]);
            }
        }
    }

    const float s  = g2[co] * rsqrtf(rv2[co] + EPS);
    const float bb = bt2[co] - rm2[co]*s;
    const float bc = b2[co];
    float* out = g_h2 + (((long)(b*32 + zz)*32 + yy)*32)*32;
    #pragma unroll
    for (int j = 0; j < 8; j++){
        float v = fmaxf((pair_sum(acc[j]) + bc)*s + bb, 0.f) * m1f[x0+j];
        out[(x0+j)*32 + co] = v;
    }
}

// ---------------- k3 v9: compact writes + 256 threads (2 blocks/SM) --------------------------
// grid (33 z-slices, 8 parity classes, 2 b), 256 threads: slot=t>>7 (2), co=t&127 (<100)
#define K3_CH 32
__global__ __launch_bounds__(256)
void k3_inv(const int* __restrict__ mask0, const float* __restrict__ binv)
{
    __shared__ __align__(16) ulonglong2 hS[K3_CH*8];   // 4KB gathered h tile
    __shared__ unsigned short alist[1089];
    __shared__ int s_na;

    const int cls = blockIdx.y;
    const int pz = cls >> 2, py = (cls >> 1) & 1, px = cls & 1;
    const int zz = pz + 2*(int)blockIdx.x;
    const int b  = blockIdx.z;
    if (zz > 64) return;

    const int nKZ = pz ? 1 : 2;
    const int nKY = py ? 1 : 2;
    const int nKX = px ? 1 : 2;
    const int nT  = nKZ*nKY*nKX;
    const int nyx = nKY*nKX;
    const int t = threadIdx.x;
    const int slot = t >> 7, co = t & 127;

    if (t == 0) s_na = 0;
    __syncthreads();

    const int nYc = py ? 32 : 33;
    const int nXc = px ? 32 : 33;
    const long plane = 274625L;              // 65^3
    const long zbase = (long)b*plane + (long)zz*4225;
    for (int f = t; f < nYc*nXc; f += 256){
        int j = f / nXc, i = f - j*nXc;
        int yy = py + 2*j, xx = px + 2*i;
        if (mask0[zbase + yy*65 + xx]){
            int p = atomicAdd(&s_na, 1);
            alist[p] = (unsigned short)((yy << 8) | xx);
        }
    }
    __syncthreads();
    const int na = s_na;
    if (na == 0) return;

    const float bc = (co < 100) ? binv[co] : 0.f;
    const ulonglong2* h2u2 = reinterpret_cast<const ulonglong2*>(g_h2);
    const ull*        wvtU = reinterpret_cast<const ull*>(g_wvt);
    const int st_site = t >> 3, st_part = t & 7;   // exactly 1 LDG per thread per tap

    for (int c0 = 0; c0 < na; c0 += K3_CH){
        const int nc = min(K3_CH, na - c0);
        ull acc[16];
        #pragma unroll
        for (int j = 0; j < 16; j++) acc[j] = 0;

        for (int ti = 0; ti < nT; ti++){
            const int zi = ti / nyx, rr = ti - zi*nyx;
            const int yi = rr / nKX, xi = rr - (rr/nKX)*nKX;
            const int q0 = pz ? ((zz-1) >> 1) : ((zz >> 1) - 1 + zi);
            if ((unsigned)q0 > 31u) continue;       // block-uniform
            const int kz = pz ? 1 : 2*zi;
            const int ky = py ? 1 : 2*yi;
            const int kx = px ? 1 : 2*xi;
            const int tap = (kz*3 + ky)*3 + kx;

            __syncthreads();                        // prev-tap compute done reading hS
            if (st_site < nc){
                const int sv = alist[c0 + st_site];
                const int yy = sv >> 8, xx = sv & 255;
                const int q1 = py ? ((yy-1) >> 1) : ((yy >> 1) - 1 + yi);
                const int qx = px ? ((xx-1) >> 1) : ((xx >> 1) - 1 + xi);
                ulonglong2 v = make_ulonglong2(0ULL, 0ULL);
                if (((unsigned)q1 <= 31u) & ((unsigned)qx <= 31u))
                    v = __ldg(h2u2 + ((((long)(b*32 + q0)*32 + q1)*32 + qx)*8 + st_part));
                hS[st_site*8 + st_part] = v;
            }
            __syncthreads();

            if (co < 100){
                ull wr[16];
                const ull* wp = wvtU + tap*1600 + co;
                #pragma unroll
                for (int cp = 0; cp < 16; cp++) wr[cp] = __ldg(wp + cp*100);

                #pragma unroll
                for (int j = 0; j < 16; j++){
                    const int ii = slot + 2*j;
                    if (ii < nc){
                        const ulonglong2* hp = hS + ii*8;
                        ull a = acc[j];
                        #pragma unroll
                        for (int k = 0; k < 4; k++){
                            ulonglong2 u = hp[2*k];
                            ulonglong2 v = hp[2*k + 1];
                            a = ffma2(u.x, wr[4*k+0], a);
                            a = ffma2(u.y, wr[4*k+1], a);
                            a = ffma2(v.x, wr[4*k+2], a);
                            a = ffma2(v.y, wr[4*k+3], a);
                        }
                        acc[j] = a;
                    }
                }
            }
        }

        if (co < 100){
            #pragma unroll
            for (int j = 0; j < 16; j++){
                const int ii = slot + 2*j;
                if (ii < nc){
                    const int sv = alist[c0 + ii];
                    const long site = zbase + (long)(sv >> 8)*65 + (sv & 255);
                    g_h3[site*100 + co] = pair_sum(acc[j]) + bc;   // coalesced 400B/site
                }
            }
        }
    }
}

// ---------------- k4 v2: expand/transpose g_h3 -> dense out, 256 thr, float4 loads ----------
// grid (65 y, 65 z, 2 b), 256 threads; smem pad-101 transpose (conflict-free reads)
__global__ __launch_bounds__(256)
void k4_expand(const int* __restrict__ mask0, float* __restrict__ out)
{
    __shared__ float v[65*101];
    __shared__ int mrow[65];

    const int yy = blockIdx.x, zz = blockIdx.y, b = blockIdx.z;
    const int t = threadIdx.x;
    const long plane = 274625L;
    const long rowbase = (long)b*plane + (long)zz*4225 + (long)yy*65;

    if (t < 65) mrow[t] = mask0[rowbase + t];
    __syncthreads();

    // load phase: float4 from g_h3 (site rows are 400B, 16B-aligned), inactive -> 0
    {
        const float4* h34 = reinterpret_cast<const float4*>(g_h3);
        for (int i = t; i < 65*25; i += 256){
            int x = i / 25, c4 = i - x*25;
            float4 val = make_float4(0.f,0.f,0.f,0.f);
            if (mrow[x]) val = h34[(rowbase + x)*25 + c4];
            float* dst = &v[x*101 + c4*4];
            dst[0] = val.x; dst[1] = val.y; dst[2] = val.z; dst[3] = val.w;
        }
    }
    __syncthreads();

    // store phase: out[b][co][z][y][x], coalesced along x
    float* ob = out + (long)b*100*plane + (long)zz*4225 + (long)yy*65;
    for (int i = t; i < 6500; i += 256){
        int co = i / 65, x = i - co*65;
        ob[(long)co*plane + x] = v[x*101 + co];
    }
}

// ---------------- launch ---------------------------------------------------------------------
extern "C" void kernel_launch(void* const* d_in, const int* in_sizes, int n_in,
                              void* d_out, int out_size)
{
    const float* x     = (const float*)d_in[0];
    const int*   mask0 = (const int*)  d_in[1];
    const float* W1    = (const float*)d_in[2];
    const float* b1    = (const float*)d_in[3];
    const float* g1    = (const float*)d_in[4];
    const float* bt1   = (const float*)d_in[5];
    const float* rm1   = (const float*)d_in[6];
    const float* rv1   = (const float*)d_in[7];
    const float* W2    = (const float*)d_in[8];
    const float* b2    = (const float*)d_in[9];
    const float* g2    = (const float*)d_in[10];
    const float* bt2   = (const float*)d_in[11];
    const float* rm2   = (const float*)d_in[12];
    const float* rv2   = (const float*)d_in[13];
    const float* Winv  = (const float*)d_in[14];
    const float* binv  = (const float*)d_in[15];
    float* out = (float*)d_out;

    k0_transpose<<<64, 256>>>(W1, W2, Winv);
    k1_conv1<<<dim3(32,32,2), 128>>>(x, mask0, b1, g1, bt1, rm1, rv1);
    k2_conv2<<<dim3(32,32,2), 128>>>(b2, g2, bt2, rm2, rv2);
    k3_inv  <<<dim3(33,8,2), 256>>>(mask0, binv);
    k4_expand<<<dim3(65,65,2), 256>>>(mask0, out);
}

// round 13
// speedup vs baseline: 1.1594x; 1.0289x over previous
#include <cuda_runtime.h>
#include <cstdint>

#define EPS 1e-5f
typedef unsigned long long ull;

// ---------------- scratch (device globals; zero-init at load; halos never written) ----------
__device__ __align__(16) float  g_h1[2*34*34*34*32];   // conv1 out, +1 halo all sides, channel-last
__device__ __align__(16) float  g_h2[2*32*32*32*32];   // conv2 out, channel-last [b][z][y][x][ci]
__device__ __align__(16) float  g_h3[2L*274625*100];   // k3 compact out, site-major [b,z,y,x][co]
__device__ unsigned char        g_m1[2*32*32*32];      // conv1 output-site mask
__device__ __align__(16) float  g_w1t[27*32];          // W1  -> [tap][co]
__device__ __align__(16) float4 g_w2q[27*8*32];        // W2  -> [tap][cp2][co], 4 ci per entry
__device__ __align__(16) float2 g_wvt[27*16*100];      // Winv-> [tap][ci/2][co]

__device__ __forceinline__ ull ffma2(ull a, ull b, ull c){
    ull d; asm("fma.rn.f32x2 %0, %1, %2, %3;" : "=l"(d) : "l"(a), "l"(b), "l"(c)); return d;
}
__device__ __forceinline__ float pair_sum(ull v){
    float lo = __uint_as_float((unsigned)(v & 0xffffffffu));
    float hi = __uint_as_float((unsigned)(v >> 32));
    return lo + hi;
}

// ---------------- k0: weight transposes -----------------------------------------------------
__global__ void k0_transpose(const float* __restrict__ W1, const float* __restrict__ W2,
                             const float* __restrict__ Wv)
{
    const int N1 = 27*32;            // g_w1t floats
    const int N2 = 27*8*32;          // g_w2q float4
    const int N3 = 27*16*100;        // g_wvt float2
    for (int i = blockIdx.x*blockDim.x + threadIdx.x; i < N1+N2+N3; i += gridDim.x*blockDim.x){
        if (i < N1){
            int tap = i >> 5, co = i & 31;
            g_w1t[i] = W1[co*27 + tap];
        } else if (i < N1+N2){
            int j = i - N1;
            int tap = j >> 8, r = j & 255, cp2 = r >> 5, co = r & 31;
            g_w2q[j] = make_float4(W2[(co*32 + 4*cp2    )*27 + tap],
                                   W2[(co*32 + 4*cp2 + 1)*27 + tap],
                                   W2[(co*32 + 4*cp2 + 2)*27 + tap],
                                   W2[(co*32 + 4*cp2 + 3)*27 + tap]);
        } else {
            int k = i - N1 - N2;
            int tap = k / 1600, r = k % 1600, cp = r / 100, co = r % 100;
            g_wvt[k] = make_float2(Wv[(co*32 + 2*cp    )*27 + tap],
                                   Wv[(co*32 + 2*cp + 1)*27 + tap]);
        }
    }
}

// ---------------- k1: conv1(s2) + BN + ReLU + mask  -> g_h1, g_m1 ----------------------------
__global__ __launch_bounds__(128)
void k1_conv1(const float* __restrict__ x, const int* __restrict__ mask0,
              const float* __restrict__ b1, const float* __restrict__ g1,
              const float* __restrict__ bt1, const float* __restrict__ rm1,
              const float* __restrict__ rv1)
{
    __shared__ float sin_[9][65];
    __shared__ int   smk[9][65];
    __shared__ float sw[27*32];
    __shared__ float m1f[32];

    const int yy = blockIdx.x, zz = blockIdx.y, b = blockIdx.z;
    const int t = threadIdx.x, co = t & 31, xg = t >> 5;

    for (int i = t; i < 9*65; i += 128){
        int r = i / 65, xx = i % 65;
        int kz = r / 3, ky = r % 3;
        int iz = 2*zz + kz, iy = 2*yy + ky;
        long off = ((long)(b*65 + iz)*65 + iy)*65 + xx;
        sin_[r][xx] = x[off];
        smk[r][xx]  = mask0[off];
    }
    for (int i = t; i < 27*32; i += 128) sw[i] = g_w1t[i];
    __syncthreads();

    if (t < 32){
        int xo = t, m = 0;
        #pragma unroll
        for (int r = 0; r < 9; r++)
            m |= smk[r][2*xo] | smk[r][2*xo+1] | smk[r][2*xo+2];
        m1f[xo] = m ? 1.0f : 0.0f;
        g_m1[((b*32 + zz)*32 + yy)*32 + xo] = m ? 1 : 0;
    }
    __syncthreads();

    const float s  = g1[co] * rsqrtf(rv1[co] + EPS);
    const float bb = bt1[co] - rm1[co]*s;
    const float bc = b1[co];

    for (int i = 0; i < 8; i++){
        int xo = xg + 4*i;
        float acc = 0.f;
        #pragma unroll
        for (int r = 0; r < 9; r++){
            #pragma unroll
            for (int kx = 0; kx < 3; kx++)
                acc = fmaf(sin_[r][2*xo + kx], sw[(r*3 + kx)*32 + co], acc);
        }
        float h = fmaxf((acc + bc)*s + bb, 0.f) * m1f[xo];
        g_h1[(((long)(b*34 + zz+1)*34 + (yy+1))*34 + (xo+1))*32 + co] = h;
    }
}

// ---------------- k2 v4: cp-pair vectorized (LDS.128 h, LDG.128 w) ---------------------------
// grid (32 y, 32 z, 2 b), 128 threads: lane=co, 4 warps x 8 outputs each.
__global__ __launch_bounds__(128)
void k2_conv2(const float* __restrict__ b2, const float* __restrict__ g2,
              const float* __restrict__ bt2, const float* __restrict__ rm2,
              const float* __restrict__ rv2)
{
    __shared__ __align__(16) float sh[9*34*32];
    __shared__ float m1f[32];

    const int yy = blockIdx.x, zz = blockIdx.y, b = blockIdx.z;
    const int t = threadIdx.x, co = t & 31, w = t >> 5;
    const int x0 = w * 8;

    {
        float4* dst = reinterpret_cast<float4*>(sh);
        for (int i = t; i < 2448; i += 128){
            int r = i / 272, rem = i % 272;
            int kz = r / 3, ky = r % 3;
            const float4* src = reinterpret_cast<const float4*>(
                g_h1 + (((long)(b*34 + zz+kz)*34 + (yy+ky))*34)*32);
            dst[r*272 + rem] = src[rem];
        }
        if (t < 32) m1f[t] = g_m1[((b*32 + zz)*32 + yy)*32 + t] ? 1.0f : 0.0f;
    }
    __syncthreads();

    const ull* shu = reinterpret_cast<const ull*>(sh);
    const ulonglong2* wq = reinterpret_cast<const ulonglong2*>(g_w2q);
    ull acc[8];
    #pragma unroll
    for (int j = 0; j < 8; j++) acc[j] = 0;

    for (int row = 0; row < 9; row++){
        const ull* base = shu + (row*34 + x0)*16;
        const ulonglong2* wb = wq + row*3*256 + co;   // [tap][cp2][co], tap stride 8*32
        #pragma unroll
        for (int cp2 = 0; cp2 < 8; cp2++){
            ulonglong2 h2[10];
            #pragma unroll
            for (int i = 0; i < 10; i++)
                h2[i] = *reinterpret_cast<const ulonglong2*>(base + i*16 + 2*cp2);
            ulonglong2 w0 = __ldg(wb +       cp2*32);
            ulonglong2 w1 = __ldg(wb + 256 + cp2*32);
            ulonglong2 w2 = __ldg(wb + 512 + cp2*32);
            #pragma unroll
            for (int j = 0; j < 8; j++){
                ull a = acc[j];
                a = ffma2(h2[j  ].x, w0.x, a);
                a = ffma2(h2[j  ].y, w0.y, a);
                a = ffma2(h2[j+1].x, w1.x, a);
                a = ffma2(h2[j+1].y, w1.y, a);
                a = ffma2(h2[j+2].x, w2.x, a);
                a = ffma2(h2[j+2].y, w2.y, a);
                acc[j] = a;
            }
        }
    }

    const float s  = g2[co] * rsqrtf(rv2[co] + EPS);
    const float bb = bt2[co] - rm2[co]*s;
    const float bc = b2[co];
    float* out = g_h2 + (((long)(b*32 + zz)*32 + yy)*32)*32;
    #pragma unroll
    for (int j = 0; j < 8; j++){
        float v = fmaxf((pair_sum(acc[j]) + bc)*s + bb, 0.f) * m1f[x0+j];
        out[(x0+j)*32 + co] = v;
    }
}

// ---------------- k3 (R11 measured-best): 512 thr, compact coalesced writes to g_h3 ----------
// grid (33 z-slices, 8 parity classes, 2 b), 512 threads: slot=t>>7, co=t&127 (<100 active)
#define K3_CH 64
__global__ __launch_bounds__(512)
void k3_inv(const int* __restrict__ mask0, const float* __restrict__ binv)
{
    __shared__ __align__(16) ulonglong2 hS[K3_CH*8];   // 8KB gathered h tile
    __shared__ unsigned short alist[1089];
    __shared__ int s_na;

    const int cls = blockIdx.y;
    const int pz = cls >> 2, py = (cls >> 1) & 1, px = cls & 1;
    const int zz = pz + 2*(int)blockIdx.x;
    const int b  = blockIdx.z;
    if (zz > 64) return;

    const int nKZ = pz ? 1 : 2;
    const int nKY = py ? 1 : 2;
    const int nKX = px ? 1 : 2;
    const int nT  = nKZ*nKY*nKX;
    const int nyx = nKY*nKX;
    const int t = threadIdx.x;
    const int slot = t >> 7, co = t & 127;

    if (t == 0) s_na = 0;
    __syncthreads();

    const int nYc = py ? 32 : 33;
    const int nXc = px ? 32 : 33;
    const long plane = 274625L;              // 65^3
    const long zbase = (long)b*plane + (long)zz*4225;
    for (int f = t; f < nYc*nXc; f += 512){
        int j = f / nXc, i = f - j*nXc;
        int yy = py + 2*j, xx = px + 2*i;
        if (mask0[zbase + yy*65 + xx]){
            int p = atomicAdd(&s_na, 1);
            alist[p] = (unsigned short)((yy << 8) | xx);
        }
    }
    __syncthreads();
    const int na = s_na;
    if (na == 0) return;

    const float bc = (co < 100) ? binv[co] : 0.f;
    const ulonglong2* h2u2 = reinterpret_cast<const ulonglong2*>(g_h2);
    const ull*        wvtU = reinterpret_cast<const ull*>(g_wvt);

    for (int c0 = 0; c0 < na; c0 += K3_CH){
        const int nc = min(K3_CH, na - c0);
        ull acc[16];
        #pragma unroll
        for (int j = 0; j < 16; j++) acc[j] = 0;

        for (int ti = 0; ti < nT; ti++){
            const int zi = ti / nyx, rr = ti - zi*nyx;
            const int yi = rr / nKX, xi = rr - (rr/nKX)*nKX;
            const int q0 = pz ? ((zz-1) >> 1) : ((zz >> 1) - 1 + zi);
            if ((unsigned)q0 > 31u) continue;       // block-uniform
            const int kz = pz ? 1 : 2*zi;
            const int ky = py ? 1 : 2*yi;
            const int kx = px ? 1 : 2*xi;
            const int tap = (kz*3 + ky)*3 + kx;

            __syncthreads();                        // prev-tap compute done reading hS
            {   // stage gathered h tile: nc sites x 128B, 8 threads/site, zeros if invalid
                const int site = t >> 3, part = t & 7;
                if (site < nc){
                    const int sv = alist[c0 + site];
                    const int yy = sv >> 8, xx = sv & 255;
                    const int q1 = py ? ((yy-1) >> 1) : ((yy >> 1) - 1 + yi);
                    const int qx = px ? ((xx-1) >> 1) : ((xx >> 1) - 1 + xi);
                    ulonglong2 v = make_ulonglong2(0ULL, 0ULL);
                    if (((unsigned)q1 <= 31u) & ((unsigned)qx <= 31u))
                        v = __ldg(h2u2 + ((((long)(b*32 + q0)*32 + q1)*32 + qx)*8 + part));
                    hS[site*8 + part] = v;
                }
            }
            __syncthreads();

            if (co < 100){
                ull wr[16];
                const ull* wp = wvtU + tap*1600 + co;
                #pragma unroll
                for (int cp = 0; cp < 16; cp++) wr[cp] = __ldg(wp + cp*100);

                #pragma unroll
                for (int j = 0; j < 16; j++){
                    const int ii = slot + 4*j;
                    if (ii < nc){
                        const ulonglong2* hp = hS + ii*8;
                        ull a = acc[j];
                        #pragma unroll
                        for (int k = 0; k < 4; k++){
                            ulonglong2 u = hp[2*k];
                            ulonglong2 v = hp[2*k + 1];
                            a = ffma2(u.x, wr[4*k+0], a);
                            a = ffma2(u.y, wr[4*k+1], a);
                            a = ffma2(v.x, wr[4*k+2], a);
                            a = ffma2(v.y, wr[4*k+3], a);
                        }
                        acc[j] = a;
                    }
                }
            }
        }

        if (co < 100){
            #pragma unroll
            for (int j = 0; j < 16; j++){
                const int ii = slot + 4*j;
                if (ii < nc){
                    const int sv = alist[c0 + ii];
                    const long site = zbase + (long)(sv >> 8)*65 + (sv & 255);
                    g_h3[site*100 + co] = pair_sum(acc[j]) + bc;   // coalesced 400B/site
                }
            }
        }
    }
}

// ---------------- k4 v2 (measured-best): expand g_h3 -> dense out, 256 thr, float4 loads -----
__global__ __launch_bounds__(256)
void k4_expand(const int* __restrict__ mask0, float* __restrict__ out)
{
    __shared__ float v[65*101];
    __shared__ int mrow[65];

    const int yy = blockIdx.x, zz = blockIdx.y, b = blockIdx.z;
    const int t = threadIdx.x;
    const long plane = 274625L;
    const long rowbase = (long)b*plane + (long)zz*4225 + (long)yy*65;

    if (t < 65) mrow[t] = mask0[rowbase + t];
    __syncthreads();

    {
        const float4* h34 = reinterpret_cast<const float4*>(g_h3);
        for (int i = t; i < 65*25; i += 256){
            int x = i / 25, c4 = i - x*25;
            float4 val = make_float4(0.f,0.f,0.f,0.f);
            if (mrow[x]) val = h34[(rowbase + x)*25 + c4];
            float* dst = &v[x*101 + c4*4];
            dst[0] = val.x; dst[1] = val.y; dst[2] = val.z; dst[3] = val.w;
        }
    }
    __syncthreads();

    float* ob = out + (long)b*100*plane + (long)zz*4225 + (long)yy*65;
    for (int i = t; i < 6500; i += 256){
        int co = i / 65, x = i - co*65;
        ob[(long)co*plane + x] = v[x*101 + co];
    }
}

// ---------------- launch ---------------------------------------------------------------------
extern "C" void kernel_launch(void* const* d_in, const int* in_sizes, int n_in,
                              void* d_out, int out_size)
{
    const float* x     = (const float*)d_in[0];
    const int*   mask0 = (const int*)  d_in[1];
    const float* W1    = (const float*)d_in[2];
    const float* b1    = (const float*)d_in[3];
    const float* g1    = (const float*)d_in[4];
    const float* bt1   = (const float*)d_in[5];
    const float* rm1   = (const float*)d_in[6];
    const float* rv1   = (const float*)d_in[7];
    const float* W2    = (const float*)d_in[8];
    const float* b2    = (const float*)d_in[9];
    const float* g2    = (const float*)d_in[10];
    const float* bt2   = (const float*)d_in[11];
    const float* rm2   = (const float*)d_in[12];
    const float* rv2   = (const float*)d_in[13];
    const float* Winv  = (const float*)d_in[14];
    const float* binv  = (const float*)d_in[15];
    float* out = (float*)d_out;

    k0_transpose<<<64, 256>>>(W1, W2, Winv);
    k1_conv1<<<dim3(32,32,2), 128>>>(x, mask0, b1, g1, bt1, rm1, rv1);
    k2_conv2<<<dim3(32,32,2), 128>>>(b2, g2, bt2, rm2, rv2);
    k3_inv  <<<dim3(33,8,2), 512>>>(mask0, binv);
    k4_expand<<<dim3(65,65,2), 256>>>(mask0, out);
}